// round 8
// baseline (speedup 1.0000x reference)
#include <cuda_runtime.h>
#include <math.h>

// CausalSTFT via Hann window + even/odd pack + 512-pt complex FFT + real recomb.
// R6: radix-8^3 register FFT (8 pts/thread, 64 threads/frame), defensive build:
//   - s_in is a native float2 array, used ONLY for input samples (no reuse)
//   - every twiddle is an independent sincospif (no chained complex powers)
//   - epilogue computes its twiddle directly (identical to the proven R3 path)
// Layouts: stage A stores B_l[r] at [72r+l]; stage B reads [72r+p+8q], writes
// D at [72r+9*m1+p]; stage C reads that, writes natural-order Z at [k].
// All verified bank-conflict-free with FSTR = 580 (== 4 mod 32).

#define HOPK 256
#define FPB  8            // frames per block
#define NT   512          // threads per block
#define TFR  2048         // frames per batch row
#define KB   513          // output bins
#define TILE_IN 2816      // samples spanned by 8 overlapping frames
#define FSTR 580          // per-frame float stride in s_re/s_im (mod 32 == 4)

__device__ __forceinline__ float2 cadd(float2 a, float2 b) { return make_float2(a.x + b.x, a.y + b.y); }
__device__ __forceinline__ float2 csub(float2 a, float2 b) { return make_float2(a.x - b.x, a.y - b.y); }
__device__ __forceinline__ float2 mul_mi(float2 a) { return make_float2(a.y, -a.x); }   // * (-i)

// v[r] <- sum_j v[j] * W8^{j r},  W8 = e^{-i pi/4}.  In-place DIF radix-8.
__device__ __forceinline__ void dif8(float2* v) {
    const float C = 0.70710678118654752440f;
    float2 u0 = cadd(v[0], v[4]), u4 = csub(v[0], v[4]);
    float2 u1 = cadd(v[1], v[5]), u5 = csub(v[1], v[5]);
    float2 u2 = cadd(v[2], v[6]), u6 = csub(v[2], v[6]);
    float2 u3 = cadd(v[3], v[7]), u7 = csub(v[3], v[7]);
    u5 = make_float2(C * (u5.x + u5.y), C * (u5.y - u5.x));   // * W8^1 =  C - iC
    u6 = mul_mi(u6);                                          // * W8^2 = -i
    u7 = make_float2(C * (u7.y - u7.x), -C * (u7.x + u7.y));  // * W8^3 = -C - iC
    float2 t0 = cadd(u0, u2), t2 = csub(u0, u2);
    float2 t1 = cadd(u1, u3), t3 = mul_mi(csub(u1, u3));
    v[0] = cadd(t0, t1); v[4] = csub(t0, t1);
    v[2] = cadd(t2, t3); v[6] = csub(t2, t3);
    t0 = cadd(u4, u6); t2 = csub(u4, u6);
    t1 = cadd(u5, u7); t3 = mul_mi(csub(u5, u7));
    v[1] = cadd(t0, t1); v[5] = csub(t0, t1);
    v[3] = cadd(t2, t3); v[7] = csub(t2, t3);
}

// v[r] *= e^{-2 pi i * (num*r) / den}, independent sincospif per power.
template<int DEN>
__device__ __forceinline__ void twiddle_rows(float2* v, int num) {
    #pragma unroll
    for (int r = 1; r < 8; ++r) {
        float s, c;
        sincospif(-(float)(num * r) * (2.0f / DEN), &s, &c);
        float xr = v[r].x, xi = v[r].y;
        v[r].x = fmaf(xr, c, -xi * s);
        v[r].y = fmaf(xr, s,  xi * c);
    }
}

__global__ __launch_bounds__(NT, 2) void causal_stft_kernel(
    const float* __restrict__ x,
    const float* __restrict__ weight,     // row 0 (first 1024 floats) = Hann window
    float* __restrict__ out)
{
    __shared__ float2 s_in[TILE_IN / 2];  // input tile as float2 (aligned), no reuse
    __shared__ float  s_re[FPB * FSTR];
    __shared__ float  s_im[FPB * FSTR];

    const int tid = threadIdx.x;
    const int b   = blockIdx.y;
    const int t0  = blockIdx.x * FPB;
    const int f   = tid >> 6;             // frame 0..7
    const int l   = tid & 63;             // lane within frame
    const float* xb = x + (size_t)b * (size_t)(HOPK * TFR);
    const int g0 = t0 * HOPK - 1023;

    // ---- stage input tile (zero-pad left edge; right edge always in-bounds) ----
    {
        float* s_inf = (float*)s_in;
        for (int u = tid; u < TILE_IN; u += NT) {
            int g = g0 + u;
            s_inf[u] = (g >= 0) ? __ldg(xb + g) : 0.0f;
        }
    }
    __syncthreads();

    float2 v[8];

    // ---- stage A: window + pack + radix-8 over j (stride 64) + W512^{l r} ----
    {
        const float2* w2 = (const float2*)weight;
        #pragma unroll
        for (int j = 0; j < 8; ++j) {
            float2 xin = s_in[f * 128 + l + 64 * j];    // (x[2m], x[2m+1]), m=l+64j
            float2 wv  = __ldg(&w2[l + 64 * j]);
            v[j] = make_float2(xin.x * wv.x, xin.y * wv.y);
        }
        dif8(v);                                        // v[r] = A_l[r]
        twiddle_rows<512>(v, l);                        // * W512^{l r}
        #pragma unroll
        for (int r = 0; r < 8; ++r) {                   // banks 8r + l : conflict-free
            s_re[f * FSTR + 72 * r + l] = v[r].x;
            s_im[f * FSTR + 72 * r + l] = v[r].y;
        }
    }
    __syncthreads();

    // ---- stage B: radix-8 over q (stride 8) + W64^{p m1} ----
    {
        const int r = l >> 3, p = l & 7;
        const int base = f * FSTR + 72 * r;
        #pragma unroll
        for (int q = 0; q < 8; ++q)                     // banks 8r+p+8q : conflict-free
            v[q] = make_float2(s_re[base + p + 8 * q], s_im[base + p + 8 * q]);
        dif8(v);                                        // v[m1] = C_{r,p}[m1]
        twiddle_rows<64>(v, p);                         // * W64^{p m1}
        __syncthreads();                                // all reads done before writes
        #pragma unroll
        for (int m1 = 0; m1 < 8; ++m1) {                // banks 8r+9m1+p : conflict-free
            s_re[base + 9 * m1 + p] = v[m1].x;
            s_im[base + 9 * m1 + p] = v[m1].y;
        }
    }
    __syncthreads();

    // ---- stage C: final radix-8 over p, write natural frequency order ----
    {
        const int r = l >> 3, m1 = l & 7;
        const int base = f * FSTR + 72 * r + 9 * m1;
        #pragma unroll
        for (int p = 0; p < 8; ++p)                     // conflict-free
            v[p] = make_float2(s_re[base + p], s_im[base + p]);
        dif8(v);                                        // v[m2] = Z[r + 8 m1 + 64 m2]
        __syncthreads();                                // all reads done before writes
        const int kb = r + 8 * m1;
        #pragma unroll
        for (int m2 = 0; m2 < 8; ++m2) {
            int k = kb + 64 * m2;
            s_re[f * FSTR + k] = v[m2].x;               // banks r+8m1 : conflict-free
            s_im[f * FSTR + k] = v[m2].y;
        }
    }
    __syncthreads();

    // ---- real-FFT recombination + magnitude, coalesced along t ----
    // X[k] = E[k] + e^{-2pi i k/1024} O[k]; E,O from Z[k], conj(Z[-k]).
    #pragma unroll
    for (int i = 0; i < 9; ++i) {
        int idx = tid + i * NT;
        if (idx < KB * FPB) {
            int ff = idx & 7;
            int k  = idx >> 3;
            int kk = k & 511;
            int km = (512 - k) & 511;
            float2 Zk = make_float2(s_re[ff * FSTR + kk], s_im[ff * FSTR + kk]);
            float2 Zm = make_float2(s_re[ff * FSTR + km], s_im[ff * FSTR + km]);
            float Er = 0.5f * (Zk.x + Zm.x);
            float Ei = 0.5f * (Zk.y - Zm.y);
            float Or = 0.5f * (Zk.y + Zm.y);
            float Oi = 0.5f * (Zm.x - Zk.x);
            float sn, cs;
            sincospif(-(float)k * (1.0f / 512.0f), &sn, &cs);   // e^{-2pi i k/1024}
            float Xr = Er + cs * Or - sn * Oi;
            float Xi = Ei + cs * Oi + sn * Or;
            float p2 = fmaf(Xr, Xr, Xi * Xi);
            out[((size_t)b * KB + k) * TFR + (t0 + ff)] = sqrtf(fmaxf(p2, 1e-12f));
        }
    }
}

extern "C" void kernel_launch(void* const* d_in, const int* in_sizes, int n_in,
                              void* d_out, int out_size)
{
    const float* x = (const float*)d_in[0];
    const float* w = (const float*)d_in[1];
    int xs = in_sizes[0];
    if (n_in >= 2 && in_sizes[0] < in_sizes[1]) {   // x is the larger tensor
        const float* t = x; x = w; w = t;
        xs = in_sizes[1];
    }
    int B = xs / (HOPK * TFR);                      // 16
    dim3 grid(TFR / FPB, B);
    causal_stft_kernel<<<grid, NT>>>(x, w, (float*)d_out);
}

// round 9
// speedup vs baseline: 2.2615x; 2.2615x over previous
#include <cuda_runtime.h>
#include <math.h>

// CausalSTFT via Hann window + even/odd pack + 512-pt complex FFT + real recomb.
// R8 = R6 structure (proven correct, L1 traffic already cut 2x) with the
// sincospif swarm removed (it made R6 issue-bound at 74% issue, 42% alu):
//   - stages A/B: 1 sincospif + chained complex powers (err ~1e-6)
//   - epilogue: W1024^k table (513 entries) filled into dead s_in space,
//     with a strided fill loop that actually covers k=512 (the R5 bug).
// Layouts unchanged: A stores [72r+l], B reads [72r+p+8q] writes [72r+9m1+p],
// C reads that and writes natural-order Z[k]; FSTR=580 (==4 mod 32) keeps the
// frame-interleaved epilogue loads conflict-free.

#define HOPK 256
#define FPB  8            // frames per block
#define NT   512          // threads per block
#define TFR  2048         // frames per batch row
#define KB   513          // output bins
#define TILE_IN 2816      // samples spanned by 8 overlapping frames
#define FSTR 580          // per-frame float stride in s_re/s_im (mod 32 == 4)

__device__ __forceinline__ float2 cmul(float2 a, float2 b) {
    return make_float2(fmaf(a.x, b.x, -a.y * b.y), fmaf(a.x, b.y, a.y * b.x));
}
__device__ __forceinline__ float2 cadd(float2 a, float2 b) { return make_float2(a.x + b.x, a.y + b.y); }
__device__ __forceinline__ float2 csub(float2 a, float2 b) { return make_float2(a.x - b.x, a.y - b.y); }
__device__ __forceinline__ float2 mul_mi(float2 a) { return make_float2(a.y, -a.x); }   // * (-i)

// v[r] <- sum_j v[j] * W8^{j r},  W8 = e^{-i pi/4}.  In-place DIF radix-8.
__device__ __forceinline__ void dif8(float2* v) {
    const float C = 0.70710678118654752440f;
    float2 u0 = cadd(v[0], v[4]), u4 = csub(v[0], v[4]);
    float2 u1 = cadd(v[1], v[5]), u5 = csub(v[1], v[5]);
    float2 u2 = cadd(v[2], v[6]), u6 = csub(v[2], v[6]);
    float2 u3 = cadd(v[3], v[7]), u7 = csub(v[3], v[7]);
    u5 = make_float2(C * (u5.x + u5.y), C * (u5.y - u5.x));   // * W8^1 =  C - iC
    u6 = mul_mi(u6);                                          // * W8^2 = -i
    u7 = make_float2(C * (u7.y - u7.x), -C * (u7.x + u7.y));  // * W8^3 = -C - iC
    float2 t0 = cadd(u0, u2), t2 = csub(u0, u2);
    float2 t1 = cadd(u1, u3), t3 = mul_mi(csub(u1, u3));
    v[0] = cadd(t0, t1); v[4] = csub(t0, t1);
    v[2] = cadd(t2, t3); v[6] = csub(t2, t3);
    t0 = cadd(u4, u6); t2 = csub(u4, u6);
    t1 = cadd(u5, u7); t3 = mul_mi(csub(u5, u7));
    v[1] = cadd(t0, t1); v[5] = csub(t0, t1);
    v[3] = cadd(t2, t3); v[7] = csub(t2, t3);
}

// v[r] *= w^r via one chained complex product (w given).
__device__ __forceinline__ void twiddle_chain(float2* v, float2 w) {
    float2 wp = w;
    v[1] = cmul(v[1], wp);
    #pragma unroll
    for (int r = 2; r < 8; ++r) { wp = cmul(wp, w); v[r] = cmul(v[r], wp); }
}

__global__ __launch_bounds__(NT, 3) void causal_stft_kernel(
    const float* __restrict__ x,
    const float* __restrict__ weight,     // row 0 (first 1024 floats) = Hann window
    float* __restrict__ out)
{
    __shared__ float2 s_in[TILE_IN / 2];  // input tile; later: W1024^k table [513]
    __shared__ float  s_re[FPB * FSTR];
    __shared__ float  s_im[FPB * FSTR];

    const int tid = threadIdx.x;
    const int b   = blockIdx.y;
    const int t0  = blockIdx.x * FPB;
    const int f   = tid >> 6;             // frame 0..7
    const int l   = tid & 63;             // lane within frame
    const float* xb = x + (size_t)b * (size_t)(HOPK * TFR);
    const int g0 = t0 * HOPK - 1023;

    // ---- stage input tile (zero-pad left edge; right edge always in-bounds) ----
    {
        float* s_inf = (float*)s_in;
        for (int u = tid; u < TILE_IN; u += NT) {
            int g = g0 + u;
            s_inf[u] = (g >= 0) ? __ldg(xb + g) : 0.0f;
        }
    }
    __syncthreads();

    float2 v[8];

    // ---- stage A: window + pack + radix-8 over j (stride 64) + W512^{l r} ----
    {
        const float2* w2 = (const float2*)weight;
        #pragma unroll
        for (int j = 0; j < 8; ++j) {
            float2 xin = s_in[f * 128 + l + 64 * j];    // (x[2m], x[2m+1]), m=l+64j
            float2 wv  = __ldg(&w2[l + 64 * j]);
            v[j] = make_float2(xin.x * wv.x, xin.y * wv.y);
        }
        dif8(v);                                        // v[r] = A_l[r]
        float s, c;
        sincospif(-(float)l * (1.0f / 256.0f), &s, &c); // W512^l
        twiddle_chain(v, make_float2(c, s));            // * W512^{l r}
        #pragma unroll
        for (int r = 0; r < 8; ++r) {                   // banks 8r + l : conflict-free
            s_re[f * FSTR + 72 * r + l] = v[r].x;
            s_im[f * FSTR + 72 * r + l] = v[r].y;
        }
    }
    __syncthreads();

    // ---- fill epilogue twiddle table into dead s_in space (ALL 513 entries) ----
    for (int j = tid; j < KB; j += NT) {
        float s, c;
        sincospif(-(float)j * (1.0f / 512.0f), &s, &c); // e^{-2pi i j/1024}
        s_in[j] = make_float2(c, s);
    }

    // ---- stage B: radix-8 over q (stride 8) + W64^{p m1} ----
    {
        const int r = l >> 3, p = l & 7;
        const int base = f * FSTR + 72 * r;
        #pragma unroll
        for (int q = 0; q < 8; ++q)                     // banks 8r+p+8q : conflict-free
            v[q] = make_float2(s_re[base + p + 8 * q], s_im[base + p + 8 * q]);
        dif8(v);                                        // v[m1] = C_{r,p}[m1]
        float s, c;
        sincospif(-(float)p * (1.0f / 32.0f), &s, &c);  // W64^p
        twiddle_chain(v, make_float2(c, s));            // * W64^{p m1}
        __syncthreads();                                // all reads done before writes
        #pragma unroll
        for (int m1 = 0; m1 < 8; ++m1) {                // banks 8r+9m1+p : conflict-free
            s_re[base + 9 * m1 + p] = v[m1].x;
            s_im[base + 9 * m1 + p] = v[m1].y;
        }
    }
    __syncthreads();

    // ---- stage C: final radix-8 over p, write natural frequency order ----
    {
        const int r = l >> 3, m1 = l & 7;
        const int base = f * FSTR + 72 * r + 9 * m1;
        #pragma unroll
        for (int p = 0; p < 8; ++p)                     // conflict-free
            v[p] = make_float2(s_re[base + p], s_im[base + p]);
        dif8(v);                                        // v[m2] = Z[r + 8 m1 + 64 m2]
        __syncthreads();                                // all reads done before writes
        const int kb = r + 8 * m1;
        #pragma unroll
        for (int m2 = 0; m2 < 8; ++m2) {
            int k = kb + 64 * m2;
            s_re[f * FSTR + k] = v[m2].x;
            s_im[f * FSTR + k] = v[m2].y;
        }
    }
    __syncthreads();

    // ---- real-FFT recombination + magnitude, coalesced along t ----
    // X[k] = E[k] + W1024^k O[k]; E,O from Z[k], conj(Z[-k]).
    #pragma unroll
    for (int i = 0; i < 9; ++i) {
        int idx = tid + i * NT;
        if (idx < KB * FPB) {
            int ff = idx & 7;
            int k  = idx >> 3;
            int kk = k & 511;
            int km = (512 - k) & 511;
            float2 Zk = make_float2(s_re[ff * FSTR + kk], s_im[ff * FSTR + kk]);
            float2 Zm = make_float2(s_re[ff * FSTR + km], s_im[ff * FSTR + km]);
            float Er = 0.5f * (Zk.x + Zm.x);
            float Ei = 0.5f * (Zk.y - Zm.y);
            float Or = 0.5f * (Zk.y + Zm.y);
            float Oi = 0.5f * (Zm.x - Zk.x);
            float2 tw = s_in[k];                        // W1024^k from table
            float Xr = Er + tw.x * Or - tw.y * Oi;
            float Xi = Ei + tw.x * Oi + tw.y * Or;
            float p2 = fmaf(Xr, Xr, Xi * Xi);
            out[((size_t)b * KB + k) * TFR + (t0 + ff)] = sqrtf(fmaxf(p2, 1e-12f));
        }
    }
}

extern "C" void kernel_launch(void* const* d_in, const int* in_sizes, int n_in,
                              void* d_out, int out_size)
{
    const float* x = (const float*)d_in[0];
    const float* w = (const float*)d_in[1];
    int xs = in_sizes[0];
    if (n_in >= 2 && in_sizes[0] < in_sizes[1]) {   // x is the larger tensor
        const float* t = x; x = w; w = t;
        xs = in_sizes[1];
    }
    int B = xs / (HOPK * TFR);                      // 16
    dim3 grid(TFR / FPB, B);
    causal_stft_kernel<<<grid, NT>>>(x, w, (float*)d_out);
}

// round 10
// speedup vs baseline: 2.4943x; 1.1029x over previous
#include <cuda_runtime.h>
#include <math.h>

// CausalSTFT via Hann window + even/odd pack + 512-pt radix-8^3 register FFT
// + Hermitian-pair recombination.
// R9 vs R8 (79.9us, issue=70.5%/L1=60.3% co-bound):
//  - merged float2 s_z (LDS.64/STS.64, half the smem instructions)
//  - stage C stores natural order IN PLACE at phi(k)=k+(k>>3) (conflict-safe)
//  - epilogue pairs (k, 512-k): X[512-k]=conj(E-tw*O) -> one load set, two outs
//  - 0.5 folded into final magnitude; sqrt.approx.f32
// ZS=578 (==2 mod 16): epilogue ff-interleaved loads conflict-free.

#define HOPK 256
#define FPB  8            // frames per block
#define NT   512          // threads per block
#define TFR  2048         // frames per batch row
#define KB   513          // output bins
#define TILE_IN 2816      // samples spanned by 8 overlapping frames
#define ZS   578          // per-frame float2 stride in s_z

__device__ __forceinline__ float2 cmul(float2 a, float2 b) {
    return make_float2(fmaf(a.x, b.x, -a.y * b.y), fmaf(a.x, b.y, a.y * b.x));
}
__device__ __forceinline__ float2 cadd(float2 a, float2 b) { return make_float2(a.x + b.x, a.y + b.y); }
__device__ __forceinline__ float2 csub(float2 a, float2 b) { return make_float2(a.x - b.x, a.y - b.y); }
__device__ __forceinline__ float2 mul_mi(float2 a) { return make_float2(a.y, -a.x); }   // * (-i)

// v[r] <- sum_j v[j] * W8^{j r},  W8 = e^{-i pi/4}.  In-place DIF radix-8.
__device__ __forceinline__ void dif8(float2* v) {
    const float C = 0.70710678118654752440f;
    float2 u0 = cadd(v[0], v[4]), u4 = csub(v[0], v[4]);
    float2 u1 = cadd(v[1], v[5]), u5 = csub(v[1], v[5]);
    float2 u2 = cadd(v[2], v[6]), u6 = csub(v[2], v[6]);
    float2 u3 = cadd(v[3], v[7]), u7 = csub(v[3], v[7]);
    u5 = make_float2(C * (u5.x + u5.y), C * (u5.y - u5.x));   // * W8^1 =  C - iC
    u6 = mul_mi(u6);                                          // * W8^2 = -i
    u7 = make_float2(C * (u7.y - u7.x), -C * (u7.x + u7.y));  // * W8^3 = -C - iC
    float2 t0 = cadd(u0, u2), t2 = csub(u0, u2);
    float2 t1 = cadd(u1, u3), t3 = mul_mi(csub(u1, u3));
    v[0] = cadd(t0, t1); v[4] = csub(t0, t1);
    v[2] = cadd(t2, t3); v[6] = csub(t2, t3);
    t0 = cadd(u4, u6); t2 = csub(u4, u6);
    t1 = cadd(u5, u7); t3 = mul_mi(csub(u5, u7));
    v[1] = cadd(t0, t1); v[5] = csub(t0, t1);
    v[3] = cadd(t2, t3); v[7] = csub(t2, t3);
}

// v[r] *= w^r via one chained complex product.
__device__ __forceinline__ void twiddle_chain(float2* v, float2 w) {
    float2 wp = w;
    v[1] = cmul(v[1], wp);
    #pragma unroll
    for (int r = 2; r < 8; ++r) { wp = cmul(wp, w); v[r] = cmul(v[r], wp); }
}

__device__ __forceinline__ float sqrt_approx(float x) {
    float r;
    asm("sqrt.approx.f32 %0, %1;" : "=f"(r) : "f"(x));
    return r;
}

__global__ __launch_bounds__(NT, 3) void causal_stft_kernel(
    const float* __restrict__ x,
    const float* __restrict__ weight,     // row 0 (first 1024 floats) = Hann window
    float* __restrict__ out)
{
    __shared__ float2 s_z[FPB * ZS];      // 36,992 B  (FFT workspace, merged re/im)
    __shared__ float2 s_in[TILE_IN / 2];  // 11,264 B  (input tile; later W1024^k table)

    const int tid = threadIdx.x;
    const int b   = blockIdx.y;
    const int t0  = blockIdx.x * FPB;
    const int f   = tid >> 6;             // frame 0..7
    const int l   = tid & 63;             // lane within frame
    const float* xb = x + (size_t)b * (size_t)(HOPK * TFR);
    const int g0 = t0 * HOPK - 1023;

    // ---- stage input tile (zero-pad left edge; right edge always in-bounds) ----
    {
        float* s_inf = (float*)s_in;
        for (int u = tid; u < TILE_IN; u += NT) {
            int g = g0 + u;
            s_inf[u] = (g >= 0) ? __ldg(xb + g) : 0.0f;
        }
    }
    __syncthreads();

    float2 v[8];
    float2* zf = s_z + f * ZS;

    // ---- stage A: window + pack + radix-8 over j (stride 64) + W512^{l r} ----
    {
        const float2* w2 = (const float2*)weight;
        #pragma unroll
        for (int j = 0; j < 8; ++j) {
            float2 xin = s_in[f * 128 + l + 64 * j];    // (x[2m], x[2m+1]), m=l+64j
            float2 wv  = __ldg(&w2[l + 64 * j]);
            v[j] = make_float2(xin.x * wv.x, xin.y * wv.y);
        }
        dif8(v);                                        // v[r] = A_l[r]
        float s, c;
        sincospif(-(float)l * (1.0f / 256.0f), &s, &c); // W512^l
        twiddle_chain(v, make_float2(c, s));            // * W512^{l r}
        #pragma unroll
        for (int r = 0; r < 8; ++r)                     // consecutive -> CF
            zf[72 * r + l] = v[r];
    }
    __syncthreads();

    // ---- fill W1024^k table (k=0..256) into dead s_in space ----
    for (int j = tid; j < 257; j += NT) {
        float s, c;
        sincospif(-(float)j * (1.0f / 512.0f), &s, &c); // e^{-2pi i j/1024}
        s_in[j] = make_float2(c, s);
    }

    // ---- stage B: radix-8 over q (stride 8) + W64^{p m1} ----
    {
        const int r = l >> 3, p = l & 7;
        float2* zr = zf + 72 * r;
        #pragma unroll
        for (int q = 0; q < 8; ++q)                     // CF (mod-16 transversal)
            v[q] = zr[p + 8 * q];
        dif8(v);                                        // v[m1] = C_{r,p}[m1]
        float s, c;
        sincospif(-(float)p * (1.0f / 32.0f), &s, &c);  // W64^p
        twiddle_chain(v, make_float2(c, s));            // * W64^{p m1}
        __syncthreads();                                // all reads before writes
        #pragma unroll
        for (int m1 = 0; m1 < 8; ++m1)                  // CF
            zr[9 * m1 + p] = v[m1];
    }
    __syncthreads();

    // ---- stage C: final radix-8 over p, store natural order at phi(k)=k+(k>>3) ----
    {
        const int r = l >> 3, m1 = l & 7;
        float2* zr = zf + 72 * r + 9 * m1;
        #pragma unroll
        for (int p = 0; p < 8; ++p)                     // CF
            v[p] = zr[p];
        dif8(v);                                        // v[m2] = Z[r + 8 m1 + 64 m2]
        __syncthreads();                                // all reads before writes
        const int base2 = r + 9 * m1;                   // phi(r+8m1+64m2) = r+9m1+72m2
        #pragma unroll
        for (int m2 = 0; m2 < 8; ++m2)
            zf[base2 + 72 * m2] = v[m2];
    }
    __syncthreads();

    // ---- Hermitian-pair recombination + magnitude ----
    // X[k]     = E + W1024^k O        (read at phi(k))
    // X[512-k] = conj(E - W1024^k O)  -> same loads, second output
    // Values here are 2E, 2O; fold the 0.5 into the final magnitude.
    {
        const int ff = tid & 7;
        const float2* ztw = s_in;
        const float2* zo  = s_z + ff * ZS;
        float* ob = out + ((size_t)b * KB) * TFR + (t0 + ff);
        int k = tid >> 3;                               // 0..63
        #pragma unroll
        for (int i = 0; i < 5; ++i, k += 64) {
            if (k <= 256) {
                int km = (512 - k) & 511;
                float2 Zk = zo[k  + (k  >> 3)];
                float2 Zm = zo[km + (km >> 3)];
                float Er = Zk.x + Zm.x;                 // 2*E
                float Ei = Zk.y - Zm.y;
                float Or = Zk.y + Zm.y;                 // 2*O
                float Oi = Zm.x - Zk.x;
                float2 tw = ztw[k];
                float tr = fmaf(tw.x, Or, -tw.y * Oi);  // 2*(tw*O)
                float ti = fmaf(tw.x, Oi,  tw.y * Or);
                float X1r = Er + tr, X1i = Ei + ti;     // 2*X[k]
                float X2r = Er - tr, X2i = Ei - ti;     // 2*conj(X[512-k])
                float p1 = fmaxf(fmaf(X1r, X1r, X1i * X1i), 4e-12f);
                float p2 = fmaxf(fmaf(X2r, X2r, X2i * X2i), 4e-12f);
                ob[(size_t)k * TFR]         = 0.5f * sqrt_approx(p1);
                ob[(size_t)(512 - k) * TFR] = 0.5f * sqrt_approx(p2);
            }
        }
    }
}

extern "C" void kernel_launch(void* const* d_in, const int* in_sizes, int n_in,
                              void* d_out, int out_size)
{
    const float* x = (const float*)d_in[0];
    const float* w = (const float*)d_in[1];
    int xs = in_sizes[0];
    if (n_in >= 2 && in_sizes[0] < in_sizes[1]) {   // x is the larger tensor
        const float* t = x; x = w; w = t;
        xs = in_sizes[1];
    }
    int B = xs / (HOPK * TFR);                      // 16
    dim3 grid(TFR / FPB, B);
    causal_stft_kernel<<<grid, NT>>>(x, w, (float*)d_out);
}